// round 1
// baseline (speedup 1.0000x reference)
#include <cuda_runtime.h>
#include <math.h>

// ---------------------------------------------------------------------------
// PretrainedGCNKNN: l2norm -> kNN(k=10) graph -> 3x (GCNConv + BN(+ReLU) + skip GEMM + residual) -> l2norm
// N=8192 nodes, D=H=2048, O=128.
// Round 1: all-fp32 baseline. One tiled SIMT GEMM (NT form: C = A * B^T) used for
// Gram + all layer GEMMs (weights pre-transposed on device each call).
// ---------------------------------------------------------------------------

#define N_NODES 8192
#define D_FEAT  2048
#define H_DIM   2048
#define O_DIM   128
#define KNN_K   10
#define N_EDGES (N_NODES * KNN_K)

// ------------------------------ scratch (device globals; no allocation) -----
__device__ float g_f [ (size_t)N_NODES * D_FEAT ];   // normalized features
__device__ float g_G [ (size_t)N_NODES * N_NODES ];  // gram matrix
__device__ float g_h [ (size_t)N_NODES * H_DIM ];    // conv GEMM out
__device__ float g_a [ (size_t)N_NODES * H_DIM ];    // post-agg/bn/relu
__device__ float g_x [ (size_t)N_NODES * D_FEAT ];   // layer output x1/x2/x3
__device__ float g_h3[ (size_t)N_NODES * O_DIM ];
__device__ float g_a3[ (size_t)N_NODES * O_DIM ];
__device__ float g_Wt[ (size_t)H_DIM * D_FEAT ];     // transposed weight staging
__device__ int   g_knn[N_EDGES];
__device__ int   g_indeg[N_NODES];
__device__ int   g_off[N_NODES + 1];
__device__ int   g_cursor[N_NODES];
__device__ int   g_csr[N_EDGES];
__device__ float g_dinv[N_NODES];

// ------------------------------ kernels ------------------------------------

// Row-wise L2 normalize: out[r] = in[r] / max(||in[r]||, 1e-12)
__global__ void k_l2norm(const float* __restrict__ in, float* __restrict__ out, int C) {
    int row = blockIdx.x;
    const float* r = in + (size_t)row * C;
    float s = 0.0f;
    for (int c = threadIdx.x; c < C; c += blockDim.x) { float v = r[c]; s += v * v; }
    __shared__ float red[256];
    red[threadIdx.x] = s;
    __syncthreads();
    for (int o = blockDim.x >> 1; o > 0; o >>= 1) {
        if (threadIdx.x < o) red[threadIdx.x] += red[threadIdx.x + o];
        __syncthreads();
    }
    float inv = 1.0f / fmaxf(sqrtf(red[0]), 1e-12f);
    float* w = out + (size_t)row * C;
    for (int c = threadIdx.x; c < C; c += blockDim.x) w[c] = r[c] * inv;
}

// Tiled fp32 GEMM, NT form: C[m,n] = sum_k A[m,k] * B[n,k]  (+bias[n] +resid[m,n])
// BM=BN=128, BK=16, 256 threads, 8x8 per thread. M%128==0, N%128==0, K%16==0.
__global__ void __launch_bounds__(256) k_gemm_nt(
    const float* __restrict__ A, const float* __restrict__ B, float* __restrict__ C,
    int M, int N, int K, const float* __restrict__ bias, const float* __restrict__ resid)
{
    __shared__ float As[16][132];
    __shared__ float Bs[16][132];
    int tid = threadIdx.x;
    int tx = tid & 15, ty = tid >> 4;
    const float* Ab = A + (size_t)(blockIdx.y * 128) * K;
    const float* Bb = B + (size_t)(blockIdx.x * 128) * K;

    float acc[8][8];
#pragma unroll
    for (int i = 0; i < 8; ++i)
#pragma unroll
        for (int j = 0; j < 8; ++j) acc[i][j] = 0.0f;

    for (int k0 = 0; k0 < K; k0 += 16) {
#pragma unroll
        for (int r = 0; r < 2; ++r) {
            int q   = tid + r * 256;       // 0..511 float4 slots per tile
            int row = q >> 2;
            int c4  = (q & 3) << 2;
            float4 va = *(const float4*)(Ab + (size_t)row * K + k0 + c4);
            As[c4 + 0][row] = va.x; As[c4 + 1][row] = va.y;
            As[c4 + 2][row] = va.z; As[c4 + 3][row] = va.w;
            float4 vb = *(const float4*)(Bb + (size_t)row * K + k0 + c4);
            Bs[c4 + 0][row] = vb.x; Bs[c4 + 1][row] = vb.y;
            Bs[c4 + 2][row] = vb.z; Bs[c4 + 3][row] = vb.w;
        }
        __syncthreads();
#pragma unroll
        for (int kk = 0; kk < 16; ++kk) {
            float a[8], b[8];
#pragma unroll
            for (int i = 0; i < 8; ++i) a[i] = As[kk][ty * 8 + i];
#pragma unroll
            for (int j = 0; j < 8; ++j) b[j] = Bs[kk][tx * 8 + j];
#pragma unroll
            for (int i = 0; i < 8; ++i)
#pragma unroll
                for (int j = 0; j < 8; ++j) acc[i][j] = fmaf(a[i], b[j], acc[i][j]);
        }
        __syncthreads();
    }

    int row0 = blockIdx.y * 128 + ty * 8;
    int col0 = blockIdx.x * 128 + tx * 8;
#pragma unroll
    for (int i = 0; i < 8; ++i) {
        size_t base = (size_t)(row0 + i) * N + col0;
#pragma unroll
        for (int j = 0; j < 8; ++j) {
            float v = acc[i][j];
            if (bias)  v += bias[col0 + j];
            if (resid) v += resid[base + j];
            C[base + j] = v;
        }
    }
}

// Transpose: out[c*R + r] = in[r*C + c]
__global__ void k_transpose(const float* __restrict__ in, float* __restrict__ out, int R, int C) {
    __shared__ float t[32][33];
    int c0 = blockIdx.x * 32, r0 = blockIdx.y * 32;
    for (int i = threadIdx.y; i < 32; i += 8) {
        int r = r0 + i, c = c0 + threadIdx.x;
        if (r < R && c < C) t[i][threadIdx.x] = in[(size_t)r * C + c];
    }
    __syncthreads();
    for (int i = threadIdx.y; i < 32; i += 8) {
        int c = c0 + i, r = r0 + threadIdx.x;
        if (r < R && c < C) out[(size_t)c * R + r] = t[threadIdx.x][i];
    }
}

// Per-row top-10 of Gram row excluding the diagonal (== knn after dropping self).
__global__ void k_topk(const float* __restrict__ G, int* __restrict__ knn) {
    __shared__ float sv[N_NODES];
    __shared__ float rv[256];
    __shared__ int   ri[256];
    int row = blockIdx.x;
    const float* g = G + (size_t)row * N_NODES;
    for (int j = threadIdx.x; j < N_NODES; j += 256) sv[j] = g[j];
    __syncthreads();
    if (threadIdx.x == 0) sv[row] = -1e30f;   // exclude self
    __syncthreads();
    for (int t = 0; t < KNN_K; ++t) {
        float bv = -1e30f; int bi = 0x7fffffff;
        for (int j = threadIdx.x; j < N_NODES; j += 256) {
            float v = sv[j];
            if (v > bv || (v == bv && j < bi)) { bv = v; bi = j; }
        }
        rv[threadIdx.x] = bv; ri[threadIdx.x] = bi;
        __syncthreads();
        for (int o = 128; o > 0; o >>= 1) {
            if (threadIdx.x < o) {
                float v2 = rv[threadIdx.x + o]; int i2 = ri[threadIdx.x + o];
                if (v2 > rv[threadIdx.x] || (v2 == rv[threadIdx.x] && i2 < ri[threadIdx.x])) {
                    rv[threadIdx.x] = v2; ri[threadIdx.x] = i2;
                }
            }
            __syncthreads();
        }
        if (threadIdx.x == 0) { knn[row * KNN_K + t] = ri[0]; sv[ri[0]] = -1e30f; }
        __syncthreads();
    }
}

__global__ void k_zero_i(int* p, int n) {
    int i = blockIdx.x * blockDim.x + threadIdx.x;
    if (i < n) p[i] = 0;
}

__global__ void k_indeg(const int* __restrict__ knn, int* __restrict__ indeg) {
    int e = blockIdx.x * blockDim.x + threadIdx.x;
    if (e < N_EDGES) atomicAdd(&indeg[knn[e]], 1);
}

__global__ void k_dinv(const int* __restrict__ indeg, float* __restrict__ dinv) {
    int i = blockIdx.x * blockDim.x + threadIdx.x;
    if (i < N_NODES) dinv[i] = rsqrtf((float)(indeg[i] + 1));
}

// Exclusive scan of indeg -> off (single block, 256 threads, 32 per thread).
__global__ void k_scan(const int* __restrict__ indeg, int* __restrict__ off) {
    __shared__ int ps[256];
    int t = threadIdx.x;
    int s = 0;
    for (int j = 0; j < 32; ++j) s += indeg[t * 32 + j];
    ps[t] = s;
    __syncthreads();
    if (t == 0) {
        int acc = 0;
        for (int i = 0; i < 256; ++i) { int v = ps[i]; ps[i] = acc; acc += v; }
        off[N_NODES] = acc;
    }
    __syncthreads();
    int acc = ps[t];
    for (int j = 0; j < 32; ++j) { off[t * 32 + j] = acc; acc += indeg[t * 32 + j]; }
}

__global__ void k_fill_csr(const int* __restrict__ knn, const int* __restrict__ off,
                           int* __restrict__ cursor, int* __restrict__ csr) {
    int e = blockIdx.x * blockDim.x + threadIdx.x;
    if (e >= N_EDGES) return;
    int s = e / KNN_K;
    int d = knn[e];
    int p = atomicAdd(&cursor[d], 1);
    csr[off[d] + p] = s;
}

// GCN aggregate (gather over incoming edges + self loop) + bias + BN(eval) [+ReLU].
// out[d,c] = BN( dinv[d] * ( dinv[d]*h[d,c] + sum_{s->d} dinv[s]*h[s,c] ) + bias[c] )
__global__ void k_agg_bn(const float* __restrict__ h, float* __restrict__ out,
                         const float* __restrict__ bias, const float* __restrict__ gamma,
                         const float* __restrict__ beta,
                         const float* __restrict__ dinv,
                         const int* __restrict__ off, const int* __restrict__ csr,
                         int C, int relu)
{
    int d = blockIdx.x;
    float dv  = dinv[d];
    int beg = off[d], end = off[d + 1];
    const float bn_rs = rsqrtf(1.0f + 1e-5f);
    for (int c = threadIdx.x; c < C; c += blockDim.x) {
        float acc = dv * h[(size_t)d * C + c];
        for (int e = beg; e < end; ++e) {
            int s = csr[e];
            acc += dinv[s] * h[(size_t)s * C + c];
        }
        float v = dv * acc + bias[c];
        v = v * (gamma[c] * bn_rs) + beta[c];
        if (relu) v = fmaxf(v, 0.0f);
        out[(size_t)d * C + c] = v;
    }
}

// ------------------------------ host launcher ------------------------------

static inline float* sym(const void* s) {
    void* p = nullptr;
    cudaGetSymbolAddress(&p, s);
    return (float*)p;
}

extern "C" void kernel_launch(void* const* d_in, const int* in_sizes, int n_in,
                              void* d_out, int out_size) {
    (void)in_sizes; (void)n_in; (void)out_size;

    const float* features = (const float*)d_in[0];
    const float* W1  = (const float*)d_in[1];
    const float* b1  = (const float*)d_in[2];
    const float* W2  = (const float*)d_in[3];
    const float* b2  = (const float*)d_in[4];
    const float* W3  = (const float*)d_in[5];
    const float* b3  = (const float*)d_in[6];
    const float* g1  = (const float*)d_in[7];
    const float* be1 = (const float*)d_in[8];
    const float* g2  = (const float*)d_in[9];
    const float* be2 = (const float*)d_in[10];
    const float* g3  = (const float*)d_in[11];
    const float* be3 = (const float*)d_in[12];
    const float* S1w = (const float*)d_in[13];
    const float* S1b = (const float*)d_in[14];
    const float* S2w = (const float*)d_in[15];
    const float* S2b = (const float*)d_in[16];
    const float* S3w = (const float*)d_in[17];
    const float* S3b = (const float*)d_in[18];
    float* out = (float*)d_out;

    float* f   = sym(g_f);
    float* G   = sym(g_G);
    float* h   = sym(g_h);
    float* a   = sym(g_a);
    float* x   = sym(g_x);
    float* h3  = sym(g_h3);
    float* a3  = sym(g_a3);
    float* Wt  = sym(g_Wt);
    int*   knn    = (int*)sym(g_knn);
    int*   indeg  = (int*)sym(g_indeg);
    int*   off    = (int*)sym(g_off);
    int*   cursor = (int*)sym(g_cursor);
    int*   csr    = (int*)sym(g_csr);
    float* dinv   = sym(g_dinv);

    dim3 tb256(256);
    dim3 trTB(32, 8);
    dim3 trG2048(2048 / 32, 2048 / 32);
    dim3 trG_W3(O_DIM / 32, 2048 / 32);   // W3: R=2048, C=128
    dim3 trG_S3(2048 / 32, O_DIM / 32);   // S3w: R=128, C=2048

    // 1. normalize
    k_l2norm<<<N_NODES, 256>>>(features, f, D_FEAT);

    // 2. Gram + KNN
    k_gemm_nt<<<dim3(N_NODES / 128, N_NODES / 128), tb256>>>(
        f, f, G, N_NODES, N_NODES, D_FEAT, nullptr, nullptr);
    k_topk<<<N_NODES, 256>>>(G, knn);

    // 3. degrees + reverse CSR
    k_zero_i<<<(N_NODES + 255) / 256, tb256>>>(indeg, N_NODES);
    k_zero_i<<<(N_NODES + 255) / 256, tb256>>>(cursor, N_NODES);
    k_indeg<<<(N_EDGES + 255) / 256, tb256>>>(knn, indeg);
    k_dinv<<<(N_NODES + 255) / 256, tb256>>>(indeg, dinv);
    k_scan<<<1, 256>>>(indeg, off);
    k_fill_csr<<<(N_EDGES + 255) / 256, tb256>>>(knn, off, cursor, csr);

    // ---- layer 1 ----
    k_transpose<<<trG2048, trTB>>>(W1, Wt, D_FEAT, H_DIM);
    k_gemm_nt<<<dim3(H_DIM / 128, N_NODES / 128), tb256>>>(
        f, Wt, h, N_NODES, H_DIM, D_FEAT, nullptr, nullptr);
    k_agg_bn<<<N_NODES, 256>>>(h, a, b1, g1, be1, dinv, off, csr, H_DIM, 1);
    k_transpose<<<trG2048, trTB>>>(S1w, Wt, H_DIM, D_FEAT);
    k_gemm_nt<<<dim3(D_FEAT / 128, N_NODES / 128), tb256>>>(
        a, Wt, x, N_NODES, D_FEAT, H_DIM, S1b, f);

    // ---- layer 2 ----
    k_transpose<<<trG2048, trTB>>>(W2, Wt, H_DIM, H_DIM);
    k_gemm_nt<<<dim3(H_DIM / 128, N_NODES / 128), tb256>>>(
        x, Wt, h, N_NODES, H_DIM, H_DIM, nullptr, nullptr);
    k_agg_bn<<<N_NODES, 256>>>(h, a, b2, g2, be2, dinv, off, csr, H_DIM, 1);
    k_transpose<<<trG2048, trTB>>>(S2w, Wt, H_DIM, D_FEAT);
    k_gemm_nt<<<dim3(D_FEAT / 128, N_NODES / 128), tb256>>>(
        a, Wt, x, N_NODES, D_FEAT, H_DIM, S2b, f);

    // ---- layer 3 ----
    k_transpose<<<trG_W3, trTB>>>(W3, Wt, H_DIM, O_DIM);
    k_gemm_nt<<<dim3(O_DIM / 128, N_NODES / 128), tb256>>>(
        x, Wt, h3, N_NODES, O_DIM, H_DIM, nullptr, nullptr);
    k_agg_bn<<<N_NODES, 128>>>(h3, a3, b3, g3, be3, dinv, off, csr, O_DIM, 0);
    k_transpose<<<trG_S3, trTB>>>(S3w, Wt, O_DIM, D_FEAT);
    k_gemm_nt<<<dim3(D_FEAT / 128, N_NODES / 128), tb256>>>(
        a3, Wt, x, N_NODES, D_FEAT, O_DIM, S3b, f);

    // 4. final l2norm -> output
    k_l2norm<<<N_NODES, 256>>>(x, out, D_FEAT);
}

// round 4
// speedup vs baseline: 1.6196x; 1.6196x over previous
#include <cuda_runtime.h>
#include <cuda_bf16.h>
#include <math.h>
#include <mma.h>
#include <cstdint>

using namespace nvcuda;

// ---------------------------------------------------------------------------
// PretrainedGCNKNN, Round 4: split-precision bf16 tensor-core GEMMs (wmma,
// m16n16k16, fp32 accum). Every GEMM: x = h + l (bf16 hi/lo), 3 passes
// (hh, hl, lh) -> ~2^-18 input precision, fp32-grade results. KNN graph
// therefore exact. 128x128x32 tiles, double-buffered smem, LDG prefetch.
// ---------------------------------------------------------------------------

#define N_NODES 8192
#define D_FEAT  2048
#define H_DIM   2048
#define O_DIM   128
#define KNN_K   10
#define N_EDGES (N_NODES * KNN_K)

// ------------------------------ scratch (device globals; no allocation) -----
__device__ float g_f [ (size_t)N_NODES * D_FEAT ];
__device__ float g_G [ (size_t)N_NODES * N_NODES ];
__device__ float g_h [ (size_t)N_NODES * H_DIM ];
__device__ float g_a [ (size_t)N_NODES * H_DIM ];
__device__ float g_x [ (size_t)N_NODES * D_FEAT ];
__device__ float g_h3[ (size_t)N_NODES * O_DIM ];
__device__ float g_a3[ (size_t)N_NODES * O_DIM ];
__device__ float g_Wt[ (size_t)H_DIM * D_FEAT ];
__device__ int   g_knn[N_EDGES];
__device__ int   g_indeg[N_NODES];
__device__ int   g_off[N_NODES + 1];
__device__ int   g_cursor[N_NODES];
__device__ int   g_csr[N_EDGES];
__device__ float g_dinv[N_NODES];

// ------------------------------ GEMM ---------------------------------------
// NT form: C[m,n] = sum_k A[m,k] * B[n,k]. BM=BN=128, BK=32, 256 threads.
// smem per buffer: Ah, Al, Bh, Bl tiles of [128][LDT] bf16.
#define LDT 40
#define TILE_E (128 * LDT)                    // bf16 elements per tile
#define BUF_E  (4 * TILE_E)                   // elements per buffer
#define SMEM_GEMM (2 * BUF_E * (int)sizeof(__nv_bfloat16))   // 81920 B

__device__ __forceinline__ uint2 pack_hi_lo(float4 v, uint2* lo_out) {
    union { __nv_bfloat16 b[4]; uint2 u; } h, l;
    float vv[4] = {v.x, v.y, v.z, v.w};
#pragma unroll
    for (int e = 0; e < 4; ++e) {
        h.b[e] = __float2bfloat16(vv[e]);
        l.b[e] = __float2bfloat16(vv[e] - __bfloat162float(h.b[e]));
    }
    *lo_out = l.u;
    return h.u;
}

__global__ void __launch_bounds__(256) k_gemm_bf3(
    const float* __restrict__ A, const float* __restrict__ B, float* __restrict__ C,
    int M, int N, int K)
{
    extern __shared__ __nv_bfloat16 sm[];

    int tid = threadIdx.x;
    int warpId = tid >> 5;
    int warpM = warpId & 3;       // 4 warps along M: 32-row slices
    int warpN = warpId >> 2;      // 2 warps along N: 64-col slices

    const float* Ab = A + (size_t)(blockIdx.y * 128) * K;
    const float* Bb = B + (size_t)(blockIdx.x * 128) * K;

    wmma::fragment<wmma::accumulator, 16, 16, 16, float> acc[2][4];
#pragma unroll
    for (int i = 0; i < 2; ++i)
#pragma unroll
        for (int j = 0; j < 4; ++j) wmma::fill_fragment(acc[i][j], 0.0f);

    const int NC = K >> 5;     // K / 32
    float4 rA[4], rB[4];

    // ---- prologue: load + stage chunk 0 ----
#pragma unroll
    for (int i = 0; i < 4; ++i) {
        int s = tid + i * 256;
        int row = s >> 3, c4 = (s & 7) << 2;
        rA[i] = *(const float4*)(Ab + (size_t)row * K + c4);
        rB[i] = *(const float4*)(Bb + (size_t)row * K + c4);
    }
    {
        __nv_bfloat16* Ah = sm;             __nv_bfloat16* Al = sm + TILE_E;
        __nv_bfloat16* Bh = sm + 2*TILE_E;  __nv_bfloat16* Bl = sm + 3*TILE_E;
#pragma unroll
        for (int i = 0; i < 4; ++i) {
            int s = tid + i * 256;
            int row = s >> 3, c4 = (s & 7) << 2;
            uint2 lo, hi;
            hi = pack_hi_lo(rA[i], &lo);
            *(uint2*)(Ah + row * LDT + c4) = hi;
            *(uint2*)(Al + row * LDT + c4) = lo;
            hi = pack_hi_lo(rB[i], &lo);
            *(uint2*)(Bh + row * LDT + c4) = hi;
            *(uint2*)(Bl + row * LDT + c4) = lo;
        }
    }
    __syncthreads();

    for (int c = 0; c < NC; ++c) {
        // prefetch next chunk to registers
        if (c + 1 < NC) {
            int c0 = (c + 1) << 5;
#pragma unroll
            for (int i = 0; i < 4; ++i) {
                int s = tid + i * 256;
                int row = s >> 3, c4 = (s & 7) << 2;
                rA[i] = *(const float4*)(Ab + (size_t)row * K + c0 + c4);
                rB[i] = *(const float4*)(Bb + (size_t)row * K + c0 + c4);
            }
        }

        // compute on buffer c&1
        {
            const __nv_bfloat16* base = sm + (c & 1) * BUF_E;
            const __nv_bfloat16* Ah = base;
            const __nv_bfloat16* Al = base + TILE_E;
            const __nv_bfloat16* Bh = base + 2*TILE_E;
            const __nv_bfloat16* Bl = base + 3*TILE_E;
#pragma unroll
            for (int ks = 0; ks < 2; ++ks) {
                wmma::fragment<wmma::matrix_a, 16, 16, 16, __nv_bfloat16, wmma::row_major> fah[2], fal[2];
                wmma::fragment<wmma::matrix_b, 16, 16, 16, __nv_bfloat16, wmma::col_major> fbh[4], fbl[4];
#pragma unroll
                for (int i = 0; i < 2; ++i) {
                    int r0 = warpM * 32 + i * 16;
                    wmma::load_matrix_sync(fah[i], Ah + r0 * LDT + ks * 16, LDT);
                    wmma::load_matrix_sync(fal[i], Al + r0 * LDT + ks * 16, LDT);
                }
#pragma unroll
                for (int j = 0; j < 4; ++j) {
                    int n0 = warpN * 64 + j * 16;
                    wmma::load_matrix_sync(fbh[j], Bh + n0 * LDT + ks * 16, LDT);
                    wmma::load_matrix_sync(fbl[j], Bl + n0 * LDT + ks * 16, LDT);
                }
#pragma unroll
                for (int i = 0; i < 2; ++i)
#pragma unroll
                    for (int j = 0; j < 4; ++j) {
                        wmma::mma_sync(acc[i][j], fah[i], fbh[j], acc[i][j]);
                        wmma::mma_sync(acc[i][j], fah[i], fbl[j], acc[i][j]);
                        wmma::mma_sync(acc[i][j], fal[i], fbh[j], acc[i][j]);
                    }
            }
        }

        // stage next chunk into the other buffer
        if (c + 1 < NC) {
            __nv_bfloat16* base = sm + ((c + 1) & 1) * BUF_E;
            __nv_bfloat16* Ah = base;
            __nv_bfloat16* Al = base + TILE_E;
            __nv_bfloat16* Bh = base + 2*TILE_E;
            __nv_bfloat16* Bl = base + 3*TILE_E;
#pragma unroll
            for (int i = 0; i < 4; ++i) {
                int s = tid + i * 256;
                int row = s >> 3, c4 = (s & 7) << 2;
                uint2 lo, hi;
                hi = pack_hi_lo(rA[i], &lo);
                *(uint2*)(Ah + row * LDT + c4) = hi;
                *(uint2*)(Al + row * LDT + c4) = lo;
                hi = pack_hi_lo(rB[i], &lo);
                *(uint2*)(Bh + row * LDT + c4) = hi;
                *(uint2*)(Bl + row * LDT + c4) = lo;
            }
            __syncthreads();
        }
    }

    // epilogue
#pragma unroll
    for (int i = 0; i < 2; ++i) {
        int row0 = blockIdx.y * 128 + warpM * 32 + i * 16;
#pragma unroll
        for (int j = 0; j < 4; ++j) {
            int col0 = blockIdx.x * 128 + warpN * 64 + j * 16;
            wmma::store_matrix_sync(&C[(size_t)row0 * N + col0], acc[i][j], N, wmma::mem_row_major);
        }
    }
}

// Epilogue: C[i] += bias[i % N] + resid[i]
__global__ void k_bias_resid(float* __restrict__ C, const float* __restrict__ bias,
                             const float* __restrict__ resid, int nMask, size_t total4)
{
    size_t q = (size_t)blockIdx.x * blockDim.x + threadIdx.x;
    if (q >= total4) return;
    size_t i = q * 4;
    float4 c = *(float4*)(C + i);
    float4 r = *(const float4*)(resid + i);
    int col = (int)(i & nMask);
    c.x += bias[col + 0] + r.x;
    c.y += bias[col + 1] + r.y;
    c.z += bias[col + 2] + r.z;
    c.w += bias[col + 3] + r.w;
    *(float4*)(C + i) = c;
}

// ------------------------------ other kernels ------------------------------

__global__ void k_l2norm(const float* __restrict__ in, float* __restrict__ out, int C) {
    int row = blockIdx.x;
    const float* r = in + (size_t)row * C;
    float s = 0.0f;
    for (int c = threadIdx.x; c < C; c += blockDim.x) { float v = r[c]; s += v * v; }
    __shared__ float red[256];
    red[threadIdx.x] = s;
    __syncthreads();
    for (int o = blockDim.x >> 1; o > 0; o >>= 1) {
        if (threadIdx.x < o) red[threadIdx.x] += red[threadIdx.x + o];
        __syncthreads();
    }
    float inv = 1.0f / fmaxf(sqrtf(red[0]), 1e-12f);
    float* w = out + (size_t)row * C;
    for (int c = threadIdx.x; c < C; c += blockDim.x) w[c] = r[c] * inv;
}

__global__ void k_transpose(const float* __restrict__ in, float* __restrict__ out, int R, int C) {
    __shared__ float t[32][33];
    int c0 = blockIdx.x * 32, r0 = blockIdx.y * 32;
    for (int i = threadIdx.y; i < 32; i += 8) {
        int r = r0 + i, c = c0 + threadIdx.x;
        if (r < R && c < C) t[i][threadIdx.x] = in[(size_t)r * C + c];
    }
    __syncthreads();
    for (int i = threadIdx.y; i < 32; i += 8) {
        int c = c0 + i, r = r0 + threadIdx.x;
        if (r < R && c < C) out[(size_t)c * R + r] = t[threadIdx.x][i];
    }
}

__global__ void k_topk(const float* __restrict__ G, int* __restrict__ knn) {
    __shared__ float sv[N_NODES];
    __shared__ float rv[256];
    __shared__ int   ri[256];
    int row = blockIdx.x;
    const float* g = G + (size_t)row * N_NODES;
    for (int j = threadIdx.x; j < N_NODES; j += 256) sv[j] = g[j];
    __syncthreads();
    if (threadIdx.x == 0) sv[row] = -1e30f;
    __syncthreads();
    for (int t = 0; t < KNN_K; ++t) {
        float bv = -1e30f; int bi = 0x7fffffff;
        for (int j = threadIdx.x; j < N_NODES; j += 256) {
            float v = sv[j];
            if (v > bv || (v == bv && j < bi)) { bv = v; bi = j; }
        }
        rv[threadIdx.x] = bv; ri[threadIdx.x] = bi;
        __syncthreads();
        for (int o = 128; o > 0; o >>= 1) {
            if (threadIdx.x < o) {
                float v2 = rv[threadIdx.x + o]; int i2 = ri[threadIdx.x + o];
                if (v2 > rv[threadIdx.x] || (v2 == rv[threadIdx.x] && i2 < ri[threadIdx.x])) {
                    rv[threadIdx.x] = v2; ri[threadIdx.x] = i2;
                }
            }
            __syncthreads();
        }
        if (threadIdx.x == 0) { knn[row * KNN_K + t] = ri[0]; sv[ri[0]] = -1e30f; }
        __syncthreads();
    }
}

__global__ void k_zero_i(int* p, int n) {
    int i = blockIdx.x * blockDim.x + threadIdx.x;
    if (i < n) p[i] = 0;
}
__global__ void k_indeg(const int* __restrict__ knn, int* __restrict__ indeg) {
    int e = blockIdx.x * blockDim.x + threadIdx.x;
    if (e < N_EDGES) atomicAdd(&indeg[knn[e]], 1);
}
__global__ void k_dinv(const int* __restrict__ indeg, float* __restrict__ dinv) {
    int i = blockIdx.x * blockDim.x + threadIdx.x;
    if (i < N_NODES) dinv[i] = rsqrtf((float)(indeg[i] + 1));
}
__global__ void k_scan(const int* __restrict__ indeg, int* __restrict__ off) {
    __shared__ int ps[256];
    int t = threadIdx.x;
    int s = 0;
    for (int j = 0; j < 32; ++j) s += indeg[t * 32 + j];
    ps[t] = s;
    __syncthreads();
    if (t == 0) {
        int acc = 0;
        for (int i = 0; i < 256; ++i) { int v = ps[i]; ps[i] = acc; acc += v; }
        off[N_NODES] = acc;
    }
    __syncthreads();
    int acc = ps[t];
    for (int j = 0; j < 32; ++j) { off[t * 32 + j] = acc; acc += indeg[t * 32 + j]; }
}
__global__ void k_fill_csr(const int* __restrict__ knn, const int* __restrict__ off,
                           int* __restrict__ cursor, int* __restrict__ csr) {
    int e = blockIdx.x * blockDim.x + threadIdx.x;
    if (e >= N_EDGES) return;
    int s = e / KNN_K;
    int d = knn[e];
    int p = atomicAdd(&cursor[d], 1);
    csr[off[d] + p] = s;
}

__global__ void k_agg_bn(const float* __restrict__ h, float* __restrict__ out,
                         const float* __restrict__ bias, const float* __restrict__ gamma,
                         const float* __restrict__ beta,
                         const float* __restrict__ dinv,
                         const int* __restrict__ off, const int* __restrict__ csr,
                         int C, int relu)
{
    int d = blockIdx.x;
    float dv  = dinv[d];
    int beg = off[d], end = off[d + 1];
    const float bn_rs = rsqrtf(1.0f + 1e-5f);
    for (int c = threadIdx.x; c < C; c += blockDim.x) {
        float acc = dv * h[(size_t)d * C + c];
        for (int e = beg; e < end; ++e) {
            int s = csr[e];
            acc += dinv[s] * h[(size_t)s * C + c];
        }
        float v = dv * acc + bias[c];
        v = v * (gamma[c] * bn_rs) + beta[c];
        if (relu) v = fmaxf(v, 0.0f);
        out[(size_t)d * C + c] = v;
    }
}

// ------------------------------ host launcher ------------------------------

static inline float* sym(const void* s) {
    void* p = nullptr;
    cudaGetSymbolAddress(&p, s);
    return (float*)p;
}

extern "C" void kernel_launch(void* const* d_in, const int* in_sizes, int n_in,
                              void* d_out, int out_size) {
    (void)in_sizes; (void)n_in; (void)out_size;

    const float* features = (const float*)d_in[0];
    const float* W1  = (const float*)d_in[1];
    const float* b1  = (const float*)d_in[2];
    const float* W2  = (const float*)d_in[3];
    const float* b2  = (const float*)d_in[4];
    const float* W3  = (const float*)d_in[5];
    const float* b3  = (const float*)d_in[6];
    const float* g1  = (const float*)d_in[7];
    const float* be1 = (const float*)d_in[8];
    const float* g2  = (const float*)d_in[9];
    const float* be2 = (const float*)d_in[10];
    const float* g3  = (const float*)d_in[11];
    const float* be3 = (const float*)d_in[12];
    const float* S1w = (const float*)d_in[13];
    const float* S1b = (const float*)d_in[14];
    const float* S2w = (const float*)d_in[15];
    const float* S2b = (const float*)d_in[16];
    const float* S3w = (const float*)d_in[17];
    const float* S3b = (const float*)d_in[18];
    float* out = (float*)d_out;

    float* f   = sym(g_f);
    float* G   = sym(g_G);
    float* h   = sym(g_h);
    float* a   = sym(g_a);
    float* x   = sym(g_x);
    float* h3  = sym(g_h3);
    float* a3  = sym(g_a3);
    float* Wt  = sym(g_Wt);
    int*   knn    = (int*)sym(g_knn);
    int*   indeg  = (int*)sym(g_indeg);
    int*   off    = (int*)sym(g_off);
    int*   cursor = (int*)sym(g_cursor);
    int*   csr    = (int*)sym(g_csr);
    float* dinv   = sym(g_dinv);

    cudaFuncSetAttribute(k_gemm_bf3, cudaFuncAttributeMaxDynamicSharedMemorySize, SMEM_GEMM);

    dim3 tb256(256);
    dim3 trTB(32, 8);
    dim3 trG2048(64, 64);
    dim3 trG_W3(O_DIM / 32, 64);
    dim3 trG_S3(64, O_DIM / 32);

    const size_t totalD4 = (size_t)N_NODES * D_FEAT / 4;
    const int    epiBlocks = (int)((totalD4 + 255) / 256);

    // 1. normalize
    k_l2norm<<<N_NODES, 256>>>(features, f, D_FEAT);

    // 2. Gram + KNN
    k_gemm_bf3<<<dim3(N_NODES / 128, N_NODES / 128), tb256, SMEM_GEMM>>>(
        f, f, G, N_NODES, N_NODES, D_FEAT);
    k_topk<<<N_NODES, 256>>>(G, knn);

    // 3. degrees + reverse CSR
    k_zero_i<<<(N_NODES + 255) / 256, tb256>>>(indeg, N_NODES);
    k_zero_i<<<(N_NODES + 255) / 256, tb256>>>(cursor, N_NODES);
    k_indeg<<<(N_EDGES + 255) / 256, tb256>>>(knn, indeg);
    k_dinv<<<(N_NODES + 255) / 256, tb256>>>(indeg, dinv);
    k_scan<<<1, 256>>>(indeg, off);
    k_fill_csr<<<(N_EDGES + 255) / 256, tb256>>>(knn, off, cursor, csr);

    // ---- layer 1 ----
    k_transpose<<<trG2048, trTB>>>(W1, Wt, D_FEAT, H_DIM);
    k_gemm_bf3<<<dim3(H_DIM / 128, N_NODES / 128), tb256, SMEM_GEMM>>>(
        f, Wt, h, N_NODES, H_DIM, D_FEAT);
    k_agg_bn<<<N_NODES, 256>>>(h, a, b1, g1, be1, dinv, off, csr, H_DIM, 1);
    k_transpose<<<trG2048, trTB>>>(S1w, Wt, H_DIM, D_FEAT);
    k_gemm_bf3<<<dim3(D_FEAT / 128, N_NODES / 128), tb256, SMEM_GEMM>>>(
        a, Wt, x, N_NODES, D_FEAT, H_DIM);
    k_bias_resid<<<epiBlocks, tb256>>>(x, S1b, f, D_FEAT - 1, totalD4);

    // ---- layer 2 ----
    k_transpose<<<trG2048, trTB>>>(W2, Wt, H_DIM, H_DIM);
    k_gemm_bf3<<<dim3(H_DIM / 128, N_NODES / 128), tb256, SMEM_GEMM>>>(
        x, Wt, h, N_NODES, H_DIM, H_DIM);
    k_agg_bn<<<N_NODES, 256>>>(h, a, b2, g2, be2, dinv, off, csr, H_DIM, 1);
    k_transpose<<<trG2048, trTB>>>(S2w, Wt, H_DIM, D_FEAT);
    k_gemm_bf3<<<dim3(D_FEAT / 128, N_NODES / 128), tb256, SMEM_GEMM>>>(
        a, Wt, x, N_NODES, D_FEAT, H_DIM);
    k_bias_resid<<<epiBlocks, tb256>>>(x, S2b, f, D_FEAT - 1, totalD4);

    // ---- layer 3 ----
    k_transpose<<<trG_W3, trTB>>>(W3, Wt, H_DIM, O_DIM);
    k_gemm_bf3<<<dim3(O_DIM / 128, N_NODES / 128), tb256, SMEM_GEMM>>>(
        x, Wt, h3, N_NODES, O_DIM, H_DIM);
    k_agg_bn<<<N_NODES, 128>>>(h3, a3, b3, g3, be3, dinv, off, csr, O_DIM, 0);
    k_transpose<<<trG_S3, trTB>>>(S3w, Wt, O_DIM, D_FEAT);
    k_gemm_bf3<<<dim3(D_FEAT / 128, N_NODES / 128), tb256, SMEM_GEMM>>>(
        a3, Wt, x, N_NODES, D_FEAT, O_DIM);
    k_bias_resid<<<epiBlocks, tb256>>>(x, S3b, f, D_FEAT - 1, totalD4);

    // 4. final l2norm -> output
    k_l2norm<<<N_NODES, 256>>>(x, out, D_FEAT);
}

// round 6
// speedup vs baseline: 2.3288x; 1.4379x over previous
#include <cuda_runtime.h>
#include <cuda_bf16.h>
#include <math.h>
#include <mma.h>
#include <cstdint>

using namespace nvcuda;

// ---------------------------------------------------------------------------
// PretrainedGCNKNN, Round 6 (Round 5 resubmit after infra failure):
//  - operands pre-split to bf16 hi/lo in gmem (split / split-transpose kernels)
//  - GEMM: cp.async double-buffered, 3-pass split (hh, lh, hl), wmma bf16
//  - Gram computed on lower-triangle blocks only, mirrored by col-major store
// ---------------------------------------------------------------------------

#define N_NODES 8192
#define D_FEAT  2048
#define H_DIM   2048
#define O_DIM   128
#define KNN_K   10
#define N_EDGES (N_NODES * KNN_K)

// ------------------------------ scratch ------------------------------------
__device__ float g_f [ (size_t)N_NODES * D_FEAT ];
__device__ float g_G [ (size_t)N_NODES * N_NODES ];
__device__ float g_h [ (size_t)N_NODES * H_DIM ];
__device__ float g_a [ (size_t)N_NODES * H_DIM ];
__device__ float g_x [ (size_t)N_NODES * D_FEAT ];
__device__ float g_h3[ (size_t)N_NODES * O_DIM ];
__device__ float g_a3[ (size_t)N_NODES * O_DIM ];
__device__ __nv_bfloat16 g_sh[ (size_t)N_NODES * D_FEAT ];  // A-side hi
__device__ __nv_bfloat16 g_sl[ (size_t)N_NODES * D_FEAT ];  // A-side lo
__device__ __nv_bfloat16 g_th[ (size_t)H_DIM * D_FEAT ];    // B-side (weightT) hi
__device__ __nv_bfloat16 g_tl[ (size_t)H_DIM * D_FEAT ];    // B-side (weightT) lo
__device__ int   g_knn[N_EDGES];
__device__ int   g_indeg[N_NODES];
__device__ int   g_off[N_NODES + 1];
__device__ int   g_cursor[N_NODES];
__device__ int   g_csr[N_EDGES];
__device__ float g_dinv[N_NODES];

// ------------------------------ helpers ------------------------------------

__device__ __forceinline__ uint32_t smem_u32(const void* p) {
    uint32_t a;
    asm("{ .reg .u64 t; cvta.to.shared.u64 t, %1; cvt.u32.u64 %0, t; }" : "=r"(a) : "l"(p));
    return a;
}
__device__ __forceinline__ void cpasync16(uint32_t dst, const void* src) {
    asm volatile("cp.async.cg.shared.global [%0], [%1], 16;" :: "r"(dst), "l"(src));
}
__device__ __forceinline__ void cp_commit() {
    asm volatile("cp.async.commit_group;" ::: "memory");
}
__device__ __forceinline__ void cp_wait1() {
    asm volatile("cp.async.wait_group 1;" ::: "memory");
}

__device__ __forceinline__ void split4(float4 v, uint2* hi, uint2* lo) {
    union { __nv_bfloat16 b[4]; uint2 u; } h, l;
    float vv[4] = {v.x, v.y, v.z, v.w};
#pragma unroll
    for (int e = 0; e < 4; ++e) {
        h.b[e] = __float2bfloat16(vv[e]);
        l.b[e] = __float2bfloat16(vv[e] - __bfloat162float(h.b[e]));
    }
    *hi = h.u; *lo = l.u;
}

// Split fp32 -> bf16 hi/lo, elementwise (n4 = count/4)
__global__ void k_split(const float* __restrict__ in, __nv_bfloat16* __restrict__ hi,
                        __nv_bfloat16* __restrict__ lo, size_t n4)
{
    size_t q = (size_t)blockIdx.x * blockDim.x + threadIdx.x;
    if (q >= n4) return;
    uint2 h, l;
    split4(*(const float4*)(in + q * 4), &h, &l);
    *(uint2*)(hi + q * 4) = h;
    *(uint2*)(lo + q * 4) = l;
}

// Split-transpose: in fp32 [R x C] -> hi/lo bf16 [C x R]
__global__ void k_split_t(const float* __restrict__ in, __nv_bfloat16* __restrict__ hiT,
                          __nv_bfloat16* __restrict__ loT, int R, int C)
{
    __shared__ float t[32][33];
    int c0 = blockIdx.x * 32, r0 = blockIdx.y * 32;
    for (int i = threadIdx.y; i < 32; i += 8) {
        int r = r0 + i, c = c0 + threadIdx.x;
        if (r < R && c < C) t[i][threadIdx.x] = in[(size_t)r * C + c];
    }
    __syncthreads();
    for (int i = threadIdx.y; i < 32; i += 8) {
        int c = c0 + i, r = r0 + threadIdx.x;
        if (r < R && c < C) {
            float v = t[threadIdx.x][i];
            __nv_bfloat16 h = __float2bfloat16(v);
            __nv_bfloat16 l = __float2bfloat16(v - __bfloat162float(h));
            hiT[(size_t)c * R + r] = h;
            loT[(size_t)c * R + r] = l;
        }
    }
}

// ------------------------------ GEMM ---------------------------------------
// NT form on pre-split operands: C[m,n] = sum_k A[m,k]*B[n,k] with
// A ~ Ah+Al, B ~ Bh+Bl; passes hh, lh, hl. BM=BN=128, BK=32, 256 threads.
// sym!=0: grid.x enumerates lower-triangle 128x128 block pairs of an MxM
// symmetric output; result mirrored with a col-major store.
#define LDT 40
#define TILE_E2 (128 * LDT)                  // bf16 elems per tile (10240 B)
#define STAGE_E (4 * TILE_E2)
#define SMEM_GEMM (2 * STAGE_E * (int)sizeof(__nv_bfloat16))   // 81920 B

__global__ void __launch_bounds__(256) k_gemm_pre(
    const __nv_bfloat16* __restrict__ Ah, const __nv_bfloat16* __restrict__ Al,
    const __nv_bfloat16* __restrict__ Bh, const __nv_bfloat16* __restrict__ Bl,
    float* __restrict__ C, int M, int N, int K, int sym)
{
    extern __shared__ __nv_bfloat16 sm[];
    uint32_t smb = smem_u32(sm);

    int tid = threadIdx.x;
    int warpId = tid >> 5;
    int warpM = warpId & 3;
    int warpN = warpId >> 2;

    int bx, by;
    if (sym) {
        int t = blockIdx.x;
        int bi = (int)((sqrtf(8.0f * (float)t + 1.0f) - 1.0f) * 0.5f);
        while ((bi + 1) * (bi + 2) / 2 <= t) ++bi;
        while (bi * (bi + 1) / 2 > t) --bi;
        by = bi;                       // A row block (>=)
        bx = t - bi * (bi + 1) / 2;    // B row block (<=)
    } else {
        bx = blockIdx.x; by = blockIdx.y;
    }

    const size_t a0 = (size_t)(by * 128) * K;
    const size_t b0 = (size_t)(bx * 128) * K;
    const int NC = K >> 5;

    // cp.async stage issuer: 8 x 16B per thread (4 tiles x 512 chunks)
    auto issue = [&](int c) {
        if (c < NC) {
            int kc = c << 5;
            uint32_t sb = smb + (uint32_t)((c & 1) * STAGE_E * 2);
#pragma unroll
            for (int i = 0; i < 8; ++i) {
                int q = tid + i * 256;
                int tile = q >> 9;
                int r = q & 511;
                int row = r >> 2;
                int ch = r & 3;
                uint32_t dst = sb + (uint32_t)(tile * TILE_E2 * 2 + row * (LDT * 2) + ch * 16);
                const __nv_bfloat16* src;
                if (tile == 0)      src = Ah + a0 + (size_t)row * K + kc + ch * 8;
                else if (tile == 1) src = Al + a0 + (size_t)row * K + kc + ch * 8;
                else if (tile == 2) src = Bh + b0 + (size_t)row * K + kc + ch * 8;
                else                src = Bl + b0 + (size_t)row * K + kc + ch * 8;
                cpasync16(dst, src);
            }
        }
        cp_commit();
    };

    wmma::fragment<wmma::accumulator, 16, 16, 16, float> acc[2][4];
#pragma unroll
    for (int i = 0; i < 2; ++i)
#pragma unroll
        for (int j = 0; j < 4; ++j) wmma::fill_fragment(acc[i][j], 0.0f);

    issue(0);
    issue(1);

    for (int c = 0; c < NC; ++c) {
        cp_wait1();
        __syncthreads();

        const __nv_bfloat16* base = sm + (c & 1) * STAGE_E;
        const __nv_bfloat16* tAh = base;
        const __nv_bfloat16* tAl = base + TILE_E2;
        const __nv_bfloat16* tBh = base + 2 * TILE_E2;
        const __nv_bfloat16* tBl = base + 3 * TILE_E2;

#pragma unroll
        for (int ks = 0; ks < 2; ++ks) {
            wmma::fragment<wmma::matrix_a, 16, 16, 16, __nv_bfloat16, wmma::row_major> fah[2], fal[2];
            wmma::fragment<wmma::matrix_b, 16, 16, 16, __nv_bfloat16, wmma::col_major> fbh[4], fbl[4];
#pragma unroll
            for (int i = 0; i < 2; ++i)
                wmma::load_matrix_sync(fah[i], tAh + (warpM * 32 + i * 16) * LDT + ks * 16, LDT);
#pragma unroll
            for (int j = 0; j < 4; ++j)
                wmma::load_matrix_sync(fbh[j], tBh + (warpN * 64 + j * 16) * LDT + ks * 16, LDT);
#pragma unroll
            for (int i = 0; i < 2; ++i)
#pragma unroll
                for (int j = 0; j < 4; ++j)
                    wmma::mma_sync(acc[i][j], fah[i], fbh[j], acc[i][j]);   // hh
#pragma unroll
            for (int i = 0; i < 2; ++i)
                wmma::load_matrix_sync(fal[i], tAl + (warpM * 32 + i * 16) * LDT + ks * 16, LDT);
#pragma unroll
            for (int i = 0; i < 2; ++i)
#pragma unroll
                for (int j = 0; j < 4; ++j)
                    wmma::mma_sync(acc[i][j], fal[i], fbh[j], acc[i][j]);   // lh
#pragma unroll
            for (int j = 0; j < 4; ++j)
                wmma::load_matrix_sync(fbl[j], tBl + (warpN * 64 + j * 16) * LDT + ks * 16, LDT);
#pragma unroll
            for (int i = 0; i < 2; ++i)
#pragma unroll
                for (int j = 0; j < 4; ++j)
                    wmma::mma_sync(acc[i][j], fah[i], fbl[j], acc[i][j]);   // hl
        }
        __syncthreads();
        issue(c + 2);
    }

    // epilogue
#pragma unroll
    for (int i = 0; i < 2; ++i) {
        int row0 = by * 128 + warpM * 32 + i * 16;
#pragma unroll
        for (int j = 0; j < 4; ++j) {
            int col0 = bx * 128 + warpN * 64 + j * 16;
            wmma::store_matrix_sync(&C[(size_t)row0 * N + col0], acc[i][j], N, wmma::mem_row_major);
            if (sym && by != bx)
                wmma::store_matrix_sync(&C[(size_t)col0 * N + row0], acc[i][j], N, wmma::mem_col_major);
        }
    }
}

// Epilogue: C[i] += bias[i % N] + resid[i]
__global__ void k_bias_resid(float* __restrict__ C, const float* __restrict__ bias,
                             const float* __restrict__ resid, int nMask, size_t total4)
{
    size_t q = (size_t)blockIdx.x * blockDim.x + threadIdx.x;
    if (q >= total4) return;
    size_t i = q * 4;
    float4 c = *(float4*)(C + i);
    float4 r = *(const float4*)(resid + i);
    int col = (int)(i & nMask);
    c.x += bias[col + 0] + r.x;
    c.y += bias[col + 1] + r.y;
    c.z += bias[col + 2] + r.z;
    c.w += bias[col + 3] + r.w;
    *(float4*)(C + i) = c;
}

// ------------------------------ other kernels ------------------------------

__global__ void k_l2norm(const float* __restrict__ in, float* __restrict__ out, int C) {
    int row = blockIdx.x;
    const float* r = in + (size_t)row * C;
    float s = 0.0f;
    for (int c = threadIdx.x; c < C; c += blockDim.x) { float v = r[c]; s += v * v; }
    __shared__ float red[256];
    red[threadIdx.x] = s;
    __syncthreads();
    for (int o = blockDim.x >> 1; o > 0; o >>= 1) {
        if (threadIdx.x < o) red[threadIdx.x] += red[threadIdx.x + o];
        __syncthreads();
    }
    float inv = 1.0f / fmaxf(sqrtf(red[0]), 1e-12f);
    float* w = out + (size_t)row * C;
    for (int c = threadIdx.x; c < C; c += blockDim.x) w[c] = r[c] * inv;
}

__global__ void k_topk(const float* __restrict__ G, int* __restrict__ knn) {
    __shared__ float sv[N_NODES];
    __shared__ float rv[256];
    __shared__ int   ri[256];
    int row = blockIdx.x;
    const float* g = G + (size_t)row * N_NODES;
    for (int j = threadIdx.x; j < N_NODES; j += 256) sv[j] = g[j];
    __syncthreads();
    if (threadIdx.x == 0) sv[row] = -1e30f;
    __syncthreads();
    for (int t = 0; t < KNN_K; ++t) {
        float bv = -1e30f; int bi = 0x7fffffff;
        for (int j = threadIdx.x; j < N_NODES; j += 256) {
            float v = sv[j];
            if (v > bv || (v == bv && j < bi)) { bv = v; bi = j; }
        }
        rv[threadIdx.x] = bv; ri[threadIdx.x] = bi;
        __syncthreads();
        for (int o = 128; o > 0; o >>= 1) {
            if (threadIdx.x < o) {
                float v2 = rv[threadIdx.x + o]; int i2 = ri[threadIdx.x + o];
                if (v2 > rv[threadIdx.x] || (v2 == rv[threadIdx.x] && i2 < ri[threadIdx.x])) {
                    rv[threadIdx.x] = v2; ri[threadIdx.x] = i2;
                }
            }
            __syncthreads();
        }
        if (threadIdx.x == 0) { knn[row * KNN_K + t] = ri[0]; sv[ri[0]] = -1e30f; }
        __syncthreads();
    }
}

__global__ void k_zero_i(int* p, int n) {
    int i = blockIdx.x * blockDim.x + threadIdx.x;
    if (i < n) p[i] = 0;
}
__global__ void k_indeg(const int* __restrict__ knn, int* __restrict__ indeg) {
    int e = blockIdx.x * blockDim.x + threadIdx.x;
    if (e < N_EDGES) atomicAdd(&indeg[knn[e]], 1);
}
__global__ void k_dinv(const int* __restrict__ indeg, float* __restrict__ dinv) {
    int i = blockIdx.x * blockDim.x + threadIdx.x;
    if (i < N_NODES) dinv[i] = rsqrtf((float)(indeg[i] + 1));
}
__global__ void k_scan(const int* __restrict__ indeg, int* __restrict__ off) {
    __shared__ int ps[256];
    int t = threadIdx.x;
    int s = 0;
    for (int j = 0; j < 32; ++j) s += indeg[t * 32 + j];
    ps[t] = s;
    __syncthreads();
    if (t == 0) {
        int acc = 0;
        for (int i = 0; i < 256; ++i) { int v = ps[i]; ps[i] = acc; acc += v; }
        off[N_NODES] = acc;
    }
    __syncthreads();
    int acc = ps[t];
    for (int j = 0; j < 32; ++j) { off[t * 32 + j] = acc; acc += indeg[t * 32 + j]; }
}
__global__ void k_fill_csr(const int* __restrict__ knn, const int* __restrict__ off,
                           int* __restrict__ cursor, int* __restrict__ csr) {
    int e = blockIdx.x * blockDim.x + threadIdx.x;
    if (e >= N_EDGES) return;
    int s = e / KNN_K;
    int d = knn[e];
    int p = atomicAdd(&cursor[d], 1);
    csr[off[d] + p] = s;
}

__global__ void k_agg_bn(const float* __restrict__ h, float* __restrict__ out,
                         const float* __restrict__ bias, const float* __restrict__ gamma,
                         const float* __restrict__ beta,
                         const float* __restrict__ dinv,
                         const int* __restrict__ off, const int* __restrict__ csr,
                         int C, int relu)
{
    int d = blockIdx.x;
    float dv  = dinv[d];
    int beg = off[d], end = off[d + 1];
    const float bn_rs = rsqrtf(1.0f + 1e-5f);
    for (int c = threadIdx.x; c < C; c += blockDim.x) {
        float acc = dv * h[(size_t)d * C + c];
        for (int e = beg; e < end; ++e) {
            int s = csr[e];
            acc += dinv[s] * h[(size_t)s * C + c];
        }
        float v = dv * acc + bias[c];
        v = v * (gamma[c] * bn_rs) + beta[c];
        if (relu) v = fmaxf(v, 0.0f);
        out[(size_t)d * C + c] = v;
    }
}

// ------------------------------ host launcher ------------------------------

static inline float* sym_ptr(const void* s) {
    void* p = nullptr;
    cudaGetSymbolAddress(&p, s);
    return (float*)p;
}

extern "C" void kernel_launch(void* const* d_in, const int* in_sizes, int n_in,
                              void* d_out, int out_size) {
    (void)in_sizes; (void)n_in; (void)out_size;

    const float* features = (const float*)d_in[0];
    const float* W1  = (const float*)d_in[1];
    const float* b1  = (const float*)d_in[2];
    const float* W2  = (const float*)d_in[3];
    const float* b2  = (const float*)d_in[4];
    const float* W3  = (const float*)d_in[5];
    const float* b3  = (const float*)d_in[6];
    const float* g1  = (const float*)d_in[7];
    const float* be1 = (const float*)d_in[8];
    const float* g2  = (const float*)d_in[9];
    const float* be2 = (const float*)d_in[10];
    const float* g3  = (const float*)d_in[11];
    const float* be3 = (const float*)d_in[12];
    const float* S1w = (const float*)d_in[13];
    const float* S1b = (const float*)d_in[14];
    const float* S2w = (const float*)d_in[15];
    const float* S2b = (const float*)d_in[16];
    const float* S3w = (const float*)d_in[17];
    const float* S3b = (const float*)d_in[18];
    float* out = (float*)d_out;

    float* f   = sym_ptr(g_f);
    float* G   = sym_ptr(g_G);
    float* h   = sym_ptr(g_h);
    float* a   = sym_ptr(g_a);
    float* x   = sym_ptr(g_x);
    float* h3  = sym_ptr(g_h3);
    float* a3  = sym_ptr(g_a3);
    __nv_bfloat16* sh = (__nv_bfloat16*)sym_ptr(g_sh);
    __nv_bfloat16* sl = (__nv_bfloat16*)sym_ptr(g_sl);
    __nv_bfloat16* th = (__nv_bfloat16*)sym_ptr(g_th);
    __nv_bfloat16* tl = (__nv_bfloat16*)sym_ptr(g_tl);
    int*   knn    = (int*)sym_ptr(g_knn);
    int*   indeg  = (int*)sym_ptr(g_indeg);
    int*   off    = (int*)sym_ptr(g_off);
    int*   cursor = (int*)sym_ptr(g_cursor);
    int*   csr    = (int*)sym_ptr(g_csr);
    float* dinv   = sym_ptr(g_dinv);

    cudaFuncSetAttribute(k_gemm_pre, cudaFuncAttributeMaxDynamicSharedMemorySize, SMEM_GEMM);

    dim3 tb256(256);
    dim3 trTB(32, 8);

    const size_t bigN4   = (size_t)N_NODES * D_FEAT / 4;   // 8192x2048 / 4
    const int    splBlk  = (int)((bigN4 + 255) / 256);
    const size_t a3N4    = (size_t)N_NODES * O_DIM / 4;
    const int    splBlk3 = (int)((a3N4 + 255) / 256);
    const size_t totalD4 = bigN4;
    const int    epiBlocks = splBlk;

    const int SYM_BLOCKS = (N_NODES / 128) * (N_NODES / 128 + 1) / 2;   // 2080

    // 1. normalize + split f
    k_l2norm<<<N_NODES, 256>>>(features, f, D_FEAT);
    k_split<<<splBlk, tb256>>>(f, sh, sl, bigN4);

    // 2. Gram (symmetric, lower-triangle blocks) + KNN
    k_gemm_pre<<<SYM_BLOCKS, tb256, SMEM_GEMM>>>(sh, sl, sh, sl, G,
                                                 N_NODES, N_NODES, D_FEAT, 1);
    k_topk<<<N_NODES, 256>>>(G, knn);

    // 3. degrees + reverse CSR
    k_zero_i<<<(N_NODES + 255) / 256, tb256>>>(indeg, N_NODES);
    k_zero_i<<<(N_NODES + 255) / 256, tb256>>>(cursor, N_NODES);
    k_indeg<<<(N_EDGES + 255) / 256, tb256>>>(knn, indeg);
    k_dinv<<<(N_NODES + 255) / 256, tb256>>>(indeg, dinv);
    k_scan<<<1, 256>>>(indeg, off);
    k_fill_csr<<<(N_EDGES + 255) / 256, tb256>>>(knn, off, cursor, csr);

    // ---- layer 1 ----
    k_split_t<<<dim3(H_DIM / 32, D_FEAT / 32), trTB>>>(W1, th, tl, D_FEAT, H_DIM);
    k_gemm_pre<<<dim3(H_DIM / 128, N_NODES / 128), tb256, SMEM_GEMM>>>(
        sh, sl, th, tl, h, N_NODES, H_DIM, D_FEAT, 0);
    k_agg_bn<<<N_NODES, 256>>>(h, a, b1, g1, be1, dinv, off, csr, H_DIM, 1);
    k_split<<<splBlk, tb256>>>(a, sh, sl, bigN4);
    k_split_t<<<dim3(D_FEAT / 32, H_DIM / 32), trTB>>>(S1w, th, tl, H_DIM, D_FEAT);
    k_gemm_pre<<<dim3(D_FEAT / 128, N_NODES / 128), tb256, SMEM_GEMM>>>(
        sh, sl, th, tl, x, N_NODES, D_FEAT, H_DIM, 0);
    k_bias_resid<<<epiBlocks, tb256>>>(x, S1b, f, D_FEAT - 1, totalD4);

    // ---- layer 2 ----
    k_split<<<splBlk, tb256>>>(x, sh, sl, bigN4);
    k_split_t<<<dim3(H_DIM / 32, H_DIM / 32), trTB>>>(W2, th, tl, H_DIM, H_DIM);
    k_gemm_pre<<<dim3(H_DIM / 128, N_NODES / 128), tb256, SMEM_GEMM>>>(
        sh, sl, th, tl, h, N_NODES, H_DIM, H_DIM, 0);
    k_agg_bn<<<N_NODES, 256>>>(h, a, b2, g2, be2, dinv, off, csr, H_DIM, 1);
    k_split<<<splBlk, tb256>>>(a, sh, sl, bigN4);
    k_split_t<<<dim3(D_FEAT / 32, H_DIM / 32), trTB>>>(S2w, th, tl, H_DIM, D_FEAT);
    k_gemm_pre<<<dim3(D_FEAT / 128, N_NODES / 128), tb256, SMEM_GEMM>>>(
        sh, sl, th, tl, x, N_NODES, D_FEAT, H_DIM, 0);
    k_bias_resid<<<epiBlocks, tb256>>>(x, S2b, f, D_FEAT - 1, totalD4);

    // ---- layer 3 ----
    k_split<<<splBlk, tb256>>>(x, sh, sl, bigN4);
    k_split_t<<<dim3(O_DIM / 32, H_DIM / 32), trTB>>>(W3, th, tl, H_DIM, O_DIM);
    k_gemm_pre<<<dim3(O_DIM / 128, N_NODES / 128), tb256, SMEM_GEMM>>>(
        sh, sl, th, tl, h3, N_NODES, O_DIM, H_DIM, 0);
    k_agg_bn<<<N_NODES, 128>>>(h3, a3, b3, g3, be3, dinv, off, csr, O_DIM, 0);
    k_split<<<splBlk3, tb256>>>(a3, sh, sl, a3N4);
    k_split_t<<<dim3(D_FEAT / 32, O_DIM / 32), trTB>>>(S3w, th, tl, O_DIM, D_FEAT);
    k_gemm_pre<<<dim3(D_FEAT / 128, N_NODES / 128), tb256, SMEM_GEMM>>>(
        sh, sl, th, tl, x, N_NODES, D_FEAT, O_DIM, 0);
    k_bias_resid<<<epiBlocks, tb256>>>(x, S3b, f, D_FEAT - 1, totalD4);

    // 4. final l2norm -> output
    k_l2norm<<<N_NODES, 256>>>(x, out, D_FEAT);
}